// round 15
// baseline (speedup 1.0000x reference)
#include <cuda_runtime.h>
#include <cuda_bf16.h>
#include <cstdint>

#define B_  4
#define T_  2048
#define H_  16
#define DK_ 64
#define D_  1024
#define GK  1024

// ---------------- scratch (device globals; allocation-free) ----------------
__device__ __align__(16) __nv_bfloat16 g_Qh[(size_t)B_*H_*T_*DK_];
__device__ __align__(16) __nv_bfloat16 g_Ql[(size_t)B_*H_*T_*DK_];
__device__ __align__(16) __nv_bfloat16 g_Kh[(size_t)B_*H_*T_*DK_];
__device__ __align__(16) __nv_bfloat16 g_Kl[(size_t)B_*H_*T_*DK_];
__device__ __align__(16) __nv_bfloat16 g_Vh[(size_t)B_*H_*T_*DK_];
__device__ __align__(16) __nv_bfloat16 g_Vl[(size_t)B_*H_*T_*DK_];
__device__ __align__(16) __nv_bfloat16 g_Xh[(size_t)B_*T_*D_];
__device__ __align__(16) __nv_bfloat16 g_Xl[(size_t)B_*T_*D_];
__device__ __align__(16) __nv_bfloat16 g_Ah[(size_t)B_*T_*D_];
__device__ __align__(16) __nv_bfloat16 g_Al[(size_t)B_*T_*D_];
__device__ __align__(16) __nv_bfloat16 g_Wqh[(size_t)3*D_*D_];
__device__ __align__(16) __nv_bfloat16 g_Wql[(size_t)3*D_*D_];
__device__ __align__(16) __nv_bfloat16 g_Woh[(size_t)D_*D_];
__device__ __align__(16) __nv_bfloat16 g_Wol[(size_t)D_*D_];

// ---------------- helpers ----------------
__device__ __forceinline__ uint32_t smem_u32(const void* p) {
    uint32_t a;
    asm("{ .reg .u64 t; cvta.to.shared.u64 t, %1; cvt.u32.u64 %0, t; }" : "=r"(a) : "l"(p));
    return a;
}
#define SWZ128(o) ((o) ^ (((o) >> 3) & 0x70))

#define LDMX4(r0, r1, r2, r3, addr)                                           \
    asm volatile("ldmatrix.sync.aligned.m8n8.x4.shared.b16 {%0,%1,%2,%3}, [%4];" \
                 : "=r"(r0), "=r"(r1), "=r"(r2), "=r"(r3) : "r"(addr))
#define LDMX4T(r0, r1, r2, r3, addr)                                          \
    asm volatile("ldmatrix.sync.aligned.m8n8.x4.trans.shared.b16 {%0,%1,%2,%3}, [%4];" \
                 : "=r"(r0), "=r"(r1), "=r"(r2), "=r"(r3) : "r"(addr))

#define MMA16816(d, a, b0v, b1v)                                              \
    asm volatile("mma.sync.aligned.m16n8k16.row.col.f32.bf16.bf16.f32 "       \
                 "{%0,%1,%2,%3}, {%4,%5,%6,%7}, {%8,%9}, {%0,%1,%2,%3};"      \
                 : "+f"((d)[0]), "+f"((d)[1]), "+f"((d)[2]), "+f"((d)[3])     \
                 : "r"((a)[0]), "r"((a)[1]), "r"((a)[2]), "r"((a)[3]),        \
                   "r"(b0v), "r"(b1v))

#define CP16(dst, src)                                                        \
    asm volatile("cp.async.cg.shared.global [%0], [%1], 16;" :: "r"(dst), "l"(src))
#define CP_COMMIT() asm volatile("cp.async.commit_group;" ::: "memory")
#define CP_WAIT(n)  asm volatile("cp.async.wait_group %0;" :: "n"(n) : "memory")

__device__ __forceinline__ uint32_t pack_bf16(float a, float b) {
    __nv_bfloat162 h = __floats2bfloat162_rn(a, b);
    return *(uint32_t*)&h;
}
// truncation hi/lo split: hi = top-16-bit truncation (PRMT), lo = bf16_rn(v-hi)
__device__ __forceinline__ void split2(float p0, float p1, uint32_t& hi, uint32_t& lo) {
    uint32_t u0 = __float_as_uint(p0), u1 = __float_as_uint(p1);
    hi = __byte_perm(u0, u1, 0x7632);
    float f0 = __uint_as_float(u0 & 0xFFFF0000u);
    float f1 = __uint_as_float(u1 & 0xFFFF0000u);
    lo = pack_bf16(p0 - f0, p1 - f1);
}

// ---------------- fused prep: x split + both weight transposes -------------
// grid ranges: [0,8192) split x; [8192,11264) W_qkv T; [11264,12288) W_o T
#define PREP_SPLIT_BLKS 8192
#define PREP_WQ_BLKS    3072    // (3072/32) n-blocks x (1024/32) k-blocks
#define PREP_WO_BLKS    1024
__global__ __launch_bounds__(256) void prep_all(
    const float* __restrict__ x,
    __nv_bfloat16* __restrict__ Xh, __nv_bfloat16* __restrict__ Xl,
    const float* __restrict__ Wq,
    __nv_bfloat16* __restrict__ Wqh, __nv_bfloat16* __restrict__ Wql,
    const float* __restrict__ Wo,
    __nv_bfloat16* __restrict__ Woh, __nv_bfloat16* __restrict__ Wol)
{
    __shared__ float tile[32][33];
    const int bx = blockIdx.x, tid = threadIdx.x;
    if (bx < PREP_SPLIT_BLKS) {
        const int i = bx * 256 + tid;   // n4 = 8192*256 exactly
        float4 v = ((const float4*)x)[i];
        uint2 Hu, Lu;
        split2(v.x, v.y, Hu.x, Lu.x);
        split2(v.z, v.w, Hu.y, Lu.y);
        ((uint2*)Xh)[i] = Hu;
        ((uint2*)Xl)[i] = Lu;
        return;
    }
    // transpose+split part
    const float* W; __nv_bfloat16 *Th, *Tl; int N, idx;
    if (bx < PREP_SPLIT_BLKS + PREP_WQ_BLKS) {
        idx = bx - PREP_SPLIT_BLKS; W = Wq; Th = Wqh; Tl = Wql; N = 3 * D_;
    } else {
        idx = bx - PREP_SPLIT_BLKS - PREP_WQ_BLKS; W = Wo; Th = Woh; Tl = Wol; N = D_;
    }
    const int nblk = N / 32;
    const int n0 = (idx % nblk) * 32, k0 = (idx / nblk) * 32;
    const int tx = tid & 31, ty = tid >> 5;   // 32 x 8
#pragma unroll
    for (int i = 0; i < 4; i++)
        tile[ty + 8 * i][tx] = W[(size_t)(k0 + ty + 8 * i) * N + n0 + tx];
    __syncthreads();
#pragma unroll
    for (int i = 0; i < 4; i++) {
        float v = tile[tx][ty + 8 * i];
        __nv_bfloat16 h = __float2bfloat16(v);
        size_t o = (size_t)(n0 + ty + 8 * i) * GK + k0 + tx;
        Th[o] = h;
        Tl[o] = __float2bfloat16(v - __bfloat162float(h));
    }
}

// ---------------- mma GEMM (R11 best, unchanged) ---------------------------
#define GSTG_B 32768
#define GSM_TOT (3 * GSTG_B)   // 96 KB
__global__ __launch_bounds__(256, 2) void gemm_mma(
    const __nv_bfloat16* __restrict__ Ah, const __nv_bfloat16* __restrict__ Al,
    const __nv_bfloat16* __restrict__ Bh, const __nv_bfloat16* __restrict__ Bl,
    const float* __restrict__ bias, float* __restrict__ Cf,
    __nv_bfloat16* __restrict__ oQh, __nv_bfloat16* __restrict__ oQl,
    __nv_bfloat16* __restrict__ oKh, __nv_bfloat16* __restrict__ oKl,
    __nv_bfloat16* __restrict__ oVh, __nv_bfloat16* __restrict__ oVl,
    int N, int mode)
{
    extern __shared__ char smem[];
    const uint32_t sb = smem_u32(smem);
    const int tid = threadIdx.x, lane = tid & 31, wid = tid >> 5;
    const int wm = (wid & 1) * 64, wn = (wid >> 1) * 32;
    const int m0 = blockIdx.y * 128, n0 = blockIdx.x * 128;

    float acc[4][4][4];
#pragma unroll
    for (int i = 0; i < 4; i++)
#pragma unroll
        for (int j = 0; j < 4; j++)
#pragma unroll
            for (int k = 0; k < 4; k++) acc[i][j][k] = 0.f;

    const int lr = tid >> 3, lseg = tid & 7;
    const int a_row = wm + (lane & 15), a_k16 = lane >> 4;
    const int b_row = wn + (lane & 7) + ((lane & 16) >> 1), b_k16 = (lane >> 3) & 1;

    auto issue = [&](int c, int st) {
        const int kb = c * 32;
        const uint32_t stb = sb + st * GSTG_B;
#pragma unroll
        for (int it = 0; it < 4; it++) {
            const int r = lr + 32 * it;
            const uint32_t so = SWZ128((uint32_t)(r * 128 + lseg * 16));
            const __nv_bfloat16* src = (lseg < 4)
                ? Ah + (size_t)(m0 + r) * GK + kb + lseg * 8
                : Al + (size_t)(m0 + r) * GK + kb + (lseg - 4) * 8;
            CP16(stb + so, src);
        }
#pragma unroll
        for (int it = 0; it < 4; it++) {
            const int r = lr + 32 * it;
            const uint32_t so = SWZ128((uint32_t)(r * 128 + lseg * 16));
            const __nv_bfloat16* src = (lseg < 4)
                ? Bh + (size_t)(n0 + r) * GK + kb + lseg * 8
                : Bl + (size_t)(n0 + r) * GK + kb + (lseg - 4) * 8;
            CP16(stb + 16384 + so, src);
        }
        CP_COMMIT();
    };

    issue(0, 0);
    issue(1, 1);
    for (int c = 0; c < 32; c++) {
        if (c + 1 < 32) CP_WAIT(1); else CP_WAIT(0);
        __syncthreads();
        if (c + 2 < 32) issue(c + 2, (c + 2) % 3);
        const uint32_t sA = sb + (c % 3) * GSTG_B;
        const uint32_t sB = sA + 16384;
#pragma unroll
        for (int kk = 0; kk < 2; kk++) {
            const uint32_t hA = kk * 32 + a_k16 * 16;
            const uint32_t hB = kk * 32 + b_k16 * 16;
            uint32_t bh[2][4], bl[2][4];
#pragma unroll
            for (int nj = 0; nj < 2; nj++) {
                const uint32_t base = (uint32_t)((b_row + nj * 16) * 128);
                LDMX4(bh[nj][0], bh[nj][1], bh[nj][2], bh[nj][3], sB + SWZ128(base + hB));
                LDMX4(bl[nj][0], bl[nj][1], bl[nj][2], bl[nj][3], sB + SWZ128(base + 64 + hB));
            }
#pragma unroll
            for (int mi = 0; mi < 4; mi++) {
                const uint32_t base = (uint32_t)((a_row + mi * 16) * 128);
                uint32_t ah[4], al[4];
                LDMX4(ah[0], ah[1], ah[2], ah[3], sA + SWZ128(base + hA));
                LDMX4(al[0], al[1], al[2], al[3], sA + SWZ128(base + 64 + hA));
#pragma unroll
                for (int nj = 0; nj < 2; nj++)
#pragma unroll
                    for (int q = 0; q < 2; q++)
                        MMA16816(acc[mi][nj * 2 + q], ah, bh[nj][q * 2], bh[nj][q * 2 + 1]);
#pragma unroll
                for (int nj = 0; nj < 2; nj++)
#pragma unroll
                    for (int q = 0; q < 2; q++)
                        MMA16816(acc[mi][nj * 2 + q], al, bh[nj][q * 2], bh[nj][q * 2 + 1]);
#pragma unroll
                for (int nj = 0; nj < 2; nj++)
#pragma unroll
                    for (int q = 0; q < 2; q++)
                        MMA16816(acc[mi][nj * 2 + q], ah, bl[nj][q * 2], bl[nj][q * 2 + 1]);
            }
        }
    }

    const int rl = lane >> 2, cl = (lane & 3) * 2;
#pragma unroll
    for (int mi = 0; mi < 4; mi++) {
        const int r_base = wm + mi * 16 + rl;
#pragma unroll
        for (int ni = 0; ni < 4; ni++) {
            const int cn = wn + ni * 8 + cl;
            const float2 b2 = *(const float2*)&bias[n0 + cn];
#pragma unroll
            for (int half = 0; half < 2; half++) {
                const int m = m0 + r_base + half * 8;
                float v0 = acc[mi][ni][half * 2 + 0] + b2.x;
                float v1 = acc[mi][ni][half * 2 + 1] + b2.y;
                if (mode == 0) {
                    float2 v; v.x = v0; v.y = v1;
                    *(float2*)&Cf[(size_t)m * N + n0 + cn] = v;
                } else {
                    const int b = m >> 11, t = m & 2047;
                    const int part = n0 >> 10;
                    const int d = (n0 & 1023) + cn;
                    const int h = d >> 6, dk = d & 63;
                    uint32_t hp, lw;
                    split2(v0, v1, hp, lw);
                    const size_t off = (((size_t)(b * H_ + h)) * T_ + t) * DK_ + dk;
                    __nv_bfloat16 *dh, *dl;
                    if (part == 0)      { dh = oQh; dl = oQl; }
                    else if (part == 1) { dh = oKh; dl = oKl; }
                    else                { dh = oVh; dl = oVl; }
                    *(uint32_t*)(dh + off) = hp;
                    *(uint32_t*)(dl + off) = lw;
                }
            }
        }
    }
}

// ---------------- mma.sync flash attention: 3-stage KV 128 (R11 best) ------
#define ASM_QH 0
#define ASM_QL 16384
#define ASM_KV 32768
#define AKV_KH 0
#define AKV_KL 16384
#define AKV_VH 32768
#define AKV_VL 49152
#define ASM_TOT (32768 + 3 * 65536)   // 224 KB

__global__ __launch_bounds__(256, 1) void attn_mma(
    const __nv_bfloat16* __restrict__ Qh, const __nv_bfloat16* __restrict__ Ql,
    const __nv_bfloat16* __restrict__ Kh, const __nv_bfloat16* __restrict__ Kl,
    const __nv_bfloat16* __restrict__ Vh, const __nv_bfloat16* __restrict__ Vl,
    __nv_bfloat16* __restrict__ Ah, __nv_bfloat16* __restrict__ Al)
{
    extern __shared__ char smem[];
    const uint32_t sb = smem_u32(smem);
    const int tid = threadIdx.x, lane = tid & 31, wid = tid >> 5;
    const int qt = gridDim.x - 1 - blockIdx.x;
    const int q0 = qt * 128;
    const int h = blockIdx.y, b = blockIdx.z;
    const size_t hb = ((size_t)(b * H_ + h)) * T_ * DK_;

    {   // Q tile (group 0)
#pragma unroll
        for (int it = 0; it < 4; it++) {
            const int u = tid + 256 * it;
            const int r = u >> 3, seg = u & 7;
            const uint32_t so = SWZ128((uint32_t)(r * 128 + seg * 16));
            const size_t g = hb + (size_t)(q0 + r) * DK_ + seg * 8;
            CP16(sb + ASM_QH + so, Qh + g);
            CP16(sb + ASM_QL + so, Ql + g);
        }
        CP_COMMIT();
    }

    auto issueKV = [&](int kt, int st) {
        const int k0 = kt * 128;
        const uint32_t stb = sb + ASM_KV + st * 65536;
#pragma unroll
        for (int it = 0; it < 4; it++) {
            const int u = tid + 256 * it;
            const int r = u >> 3, seg = u & 7;
            const uint32_t so = SWZ128((uint32_t)(r * 128 + seg * 16));
            const size_t g = hb + (size_t)(k0 + r) * DK_ + seg * 8;
            CP16(stb + AKV_KH + so, Kh + g);
            CP16(stb + AKV_KL + so, Kl + g);
            CP16(stb + AKV_VH + so, Vh + g);
            CP16(stb + AKV_VL + so, Vl + g);
        }
        CP_COMMIT();
    };

    const int nkt = qt;
    issueKV(0, 0);
    if (nkt >= 1) { issueKV(1, 1); CP_WAIT(2); }   // Q done
    else          { CP_WAIT(1); }
    __syncthreads();

    const int a_row = wid * 16 + (lane & 15), a_k16 = lane >> 4;
    uint32_t qfh[4][4], qfl[4][4];
#pragma unroll
    for (int kk = 0; kk < 4; kk++) {
        const uint32_t off = SWZ128((uint32_t)(a_row * 128 + kk * 32 + a_k16 * 16));
        LDMX4(qfh[kk][0], qfh[kk][1], qfh[kk][2], qfh[kk][3], sb + ASM_QH + off);
        LDMX4(qfl[kk][0], qfl[kk][1], qfl[kk][2], qfl[kk][3], sb + ASM_QL + off);
    }

    const int b_row = (lane & 7) + ((lane & 16) >> 1), b_k16 = (lane >> 3) & 1;
    const int vm = lane >> 3, vr = lane & 7;
    const int rr = lane >> 2, t2 = (lane & 3) * 2;

    float o[8][4];
#pragma unroll
    for (int i = 0; i < 8; i++)
#pragma unroll
        for (int j = 0; j < 4; j++) o[i][j] = 0.f;
    float m_r = -1e30f, m_r8 = -1e30f, l_r = 0.f, l_r8 = 0.f;

    for (int kt = 0; kt <= nkt; kt++) {
        if (kt + 1 <= nkt) CP_WAIT(1); else CP_WAIT(0);
        __syncthreads();
        if (kt + 2 <= nkt) issueKV(kt + 2, (kt + 2) % 3);
        const uint32_t stb = sb + ASM_KV + (kt % 3) * 65536;
        const int k0 = kt * 128;

        float s[16][4];
#pragma unroll
        for (int i = 0; i < 16; i++)
#pragma unroll
            for (int j = 0; j < 4; j++) s[i][j] = 0.f;
#pragma unroll
        for (int kk = 0; kk < 4; kk++) {
#pragma unroll
            for (int nn = 0; nn < 8; nn++) {
                const uint32_t off = SWZ128((uint32_t)((nn * 16 + b_row) * 128 + kk * 32 + b_k16 * 16));
                uint32_t kh[4], kl[4];
                LDMX4(kh[0], kh[1], kh[2], kh[3], stb + AKV_KH + off);
                LDMX4(kl[0], kl[1], kl[2], kl[3], stb + AKV_KL + off);
                float* s0 = s[2 * nn];
                float* s1 = s[2 * nn + 1];
                MMA16816(s0, qfh[kk], kh[0], kh[1]);
                MMA16816(s0, qfl[kk], kh[0], kh[1]);
                MMA16816(s0, qfh[kk], kl[0], kl[1]);
                MMA16816(s1, qfh[kk], kh[2], kh[3]);
                MMA16816(s1, qfl[kk], kh[2], kh[3]);
                MMA16816(s1, qfh[kk], kl[2], kl[3]);
            }
        }

        const bool diag = (k0 == q0);
        const int qi_r = q0 + wid * 16 + rr;
#pragma unroll
        for (int ni = 0; ni < 16; ni++) {
            const int kc = k0 + ni * 8 + t2;
#pragma unroll
            for (int e = 0; e < 4; e++) {
                float v = s[ni][e] * 0.125f;
                if (diag) {
                    const int kj = kc + (e & 1);
                    const int qi = qi_r + ((e >> 1) << 3);
                    if (kj > qi) v = -1e30f;
                }
                s[ni][e] = v;
            }
        }

        float rmr = -1e30f, rm8 = -1e30f;
#pragma unroll
        for (int ni = 0; ni < 16; ni++) {
            rmr = fmaxf(rmr, fmaxf(s[ni][0], s[ni][1]));
            rm8 = fmaxf(rm8, fmaxf(s[ni][2], s[ni][3]));
        }
        rmr = fmaxf(rmr, __shfl_xor_sync(0xffffffffu, rmr, 1));
        rmr = fmaxf(rmr, __shfl_xor_sync(0xffffffffu, rmr, 2));
        rm8 = fmaxf(rm8, __shfl_xor_sync(0xffffffffu, rm8, 1));
        rm8 = fmaxf(rm8, __shfl_xor_sync(0xffffffffu, rm8, 2));

        const float mnr = fmaxf(m_r, rmr), mn8 = fmaxf(m_r8, rm8);
        const float ar = __expf(m_r - mnr), a8 = __expf(m_r8 - mn8);
        m_r = mnr; m_r8 = mn8;
        l_r *= ar; l_r8 *= a8;
#pragma unroll
        for (int dn = 0; dn < 8; dn++) {
            o[dn][0] *= ar; o[dn][1] *= ar; o[dn][2] *= a8; o[dn][3] *= a8;
        }

#pragma unroll
        for (int kk = 0; kk < 8; kk++) {
            float p0 = __expf(s[2 * kk][0] - m_r);
            float p1 = __expf(s[2 * kk][1] - m_r);
            float p2 = __expf(s[2 * kk][2] - m_r8);
            float p3 = __expf(s[2 * kk][3] - m_r8);
            float p4 = __expf(s[2 * kk + 1][0] - m_r);
            float p5 = __expf(s[2 * kk + 1][1] - m_r);
            float p6 = __expf(s[2 * kk + 1][2] - m_r8);
            float p7 = __expf(s[2 * kk + 1][3] - m_r8);
            l_r  += p0 + p1 + p4 + p5;
            l_r8 += p2 + p3 + p6 + p7;

            uint32_t pH[4], pL[4];
            split2(p0, p1, pH[0], pL[0]);
            split2(p2, p3, pH[1], pL[1]);
            split2(p4, p5, pH[2], pL[2]);
            split2(p6, p7, pH[3], pL[3]);
#pragma unroll
            for (int dp = 0; dp < 4; dp++) {
                const uint32_t off = SWZ128((uint32_t)(
                    (kk * 16 + (vm & 1) * 8 + vr) * 128 + (vm >> 1) * 16 + dp * 32));
                uint32_t vh[4], vl[4];
                LDMX4T(vh[0], vh[1], vh[2], vh[3], stb + AKV_VH + off);
                LDMX4T(vl[0], vl[1], vl[2], vl[3], stb + AKV_VL + off);
                float* o0 = o[2 * dp];
                float* o1 = o[2 * dp + 1];
                MMA16816(o0, pH, vh[0], vh[1]);
                MMA16816(o0, pL, vh[0], vh[1]);
                MMA16816(o0, pH, vl[0], vl[1]);
                MMA16816(o1, pH, vh[2], vh[3]);
                MMA16816(o1, pL, vh[2], vh[3]);
                MMA16816(o1, pH, vl[2], vl[3]);
            }
        }
    }

    l_r  += __shfl_xor_sync(0xffffffffu, l_r, 1);
    l_r  += __shfl_xor_sync(0xffffffffu, l_r, 2);
    l_r8 += __shfl_xor_sync(0xffffffffu, l_r8, 1);
    l_r8 += __shfl_xor_sync(0xffffffffu, l_r8, 2);
    const float ir = 1.f / l_r, i8 = 1.f / l_r8;
    const int trow = q0 + wid * 16 + rr;
#pragma unroll
    for (int dn = 0; dn < 8; dn++) {
        float v0 = o[dn][0] * ir, v1 = o[dn][1] * ir;
        float v2 = o[dn][2] * i8, v3 = o[dn][3] * i8;
        const int col = h * DK_ + dn * 8 + t2;
        size_t o1 = ((size_t)(b * T_ + trow)) * D_ + col;
        size_t o2 = ((size_t)(b * T_ + trow + 8)) * D_ + col;
        uint32_t hp, lw;
        split2(v0, v1, hp, lw);
        *(uint32_t*)(Ah + o1) = hp; *(uint32_t*)(Al + o1) = lw;
        split2(v2, v3, hp, lw);
        *(uint32_t*)(Ah + o2) = hp; *(uint32_t*)(Al + o2) = lw;
    }
}

// ---------------------------------------------------------------------------
extern "C" void kernel_launch(void* const* d_in, const int* in_sizes, int n_in,
                              void* d_out, int out_size)
{
    const float* x     = (const float*)d_in[0];
    const float* W_qkv = (const float*)d_in[1];
    const float* b_qkv = (const float*)d_in[2];
    const float* W_o   = (const float*)d_in[3];
    const float* b_o   = (const float*)d_in[4];

    __nv_bfloat16 *Qh, *Ql, *Kh, *Kl, *Vh, *Vl, *Xh, *Xl, *Ahp, *Alp, *Wqh, *Wql, *Woh, *Wol;
    cudaGetSymbolAddress((void**)&Qh, g_Qh); cudaGetSymbolAddress((void**)&Ql, g_Ql);
    cudaGetSymbolAddress((void**)&Kh, g_Kh); cudaGetSymbolAddress((void**)&Kl, g_Kl);
    cudaGetSymbolAddress((void**)&Vh, g_Vh); cudaGetSymbolAddress((void**)&Vl, g_Vl);
    cudaGetSymbolAddress((void**)&Xh, g_Xh); cudaGetSymbolAddress((void**)&Xl, g_Xl);
    cudaGetSymbolAddress((void**)&Ahp, g_Ah); cudaGetSymbolAddress((void**)&Alp, g_Al);
    cudaGetSymbolAddress((void**)&Wqh, g_Wqh); cudaGetSymbolAddress((void**)&Wql, g_Wql);
    cudaGetSymbolAddress((void**)&Woh, g_Woh); cudaGetSymbolAddress((void**)&Wol, g_Wol);

    const int M = B_ * T_;

    // fused prep: x split + W_qkv transpose + W_o transpose (one launch)
    prep_all<<<PREP_SPLIT_BLKS + PREP_WQ_BLKS + PREP_WO_BLKS, 256>>>(
        x, Xh, Xl, W_qkv, Wqh, Wql, W_o, Woh, Wol);

    cudaFuncSetAttribute(gemm_mma, cudaFuncAttributeMaxDynamicSharedMemorySize, GSM_TOT);
    cudaFuncSetAttribute(attn_mma, cudaFuncAttributeMaxDynamicSharedMemorySize, ASM_TOT);

    // 1) QKV projection -> bf16 hi/lo head-major Q/K/V
    {
        dim3 grid(3 * D_ / 128, M / 128);
        gemm_mma<<<grid, 256, GSM_TOT>>>(Xh, Xl, Wqh, Wql, b_qkv, nullptr,
                                         Qh, Ql, Kh, Kl, Vh, Vl, 3 * D_, 1);
    }

    // 2) causal flash attention (tensor cores) -> Ah/Al bf16 hi/lo
    {
        dim3 grid(T_ / 128, H_, B_);
        attn_mma<<<grid, 256, ASM_TOT>>>(Qh, Ql, Kh, Kl, Vh, Vl, Ahp, Alp);
    }

    // 3) output projection -> fp32 d_out
    {
        dim3 grid(D_ / 128, M / 128);
        gemm_mma<<<grid, 256, GSM_TOT>>>(Ahp, Alp, Woh, Wol, b_o, (float*)d_out,
                                         nullptr, nullptr, nullptr, nullptr, nullptr, nullptr,
                                         D_, 0);
    }
}

// round 16
// speedup vs baseline: 1.7090x; 1.7090x over previous
#include <cuda_runtime.h>
#include <cuda_bf16.h>
#include <cuda_fp16.h>
#include <cstdint>

#define B_  4
#define T_  2048
#define H_  16
#define DK_ 64
#define D_  1024
#define GK  1024

// ---------------- scratch (device globals; allocation-free) ----------------
__device__ __align__(16) __nv_bfloat16 g_Qh[(size_t)B_*H_*T_*DK_];
__device__ __align__(16) __nv_bfloat16 g_Ql[(size_t)B_*H_*T_*DK_];
__device__ __align__(16) __nv_bfloat16 g_Kh[(size_t)B_*H_*T_*DK_];
__device__ __align__(16) __nv_bfloat16 g_Kl[(size_t)B_*H_*T_*DK_];
__device__ __align__(16) __half        g_Vf[(size_t)B_*H_*T_*DK_];   // V in fp16
__device__ __align__(16) __nv_bfloat16 g_Xh[(size_t)B_*T_*D_];
__device__ __align__(16) __nv_bfloat16 g_Xl[(size_t)B_*T_*D_];
__device__ __align__(16) __nv_bfloat16 g_Ah[(size_t)B_*T_*D_];
__device__ __align__(16) __nv_bfloat16 g_Al[(size_t)B_*T_*D_];
__device__ __align__(16) __nv_bfloat16 g_Wqh[(size_t)3*D_*D_];
__device__ __align__(16) __nv_bfloat16 g_Wql[(size_t)3*D_*D_];
__device__ __align__(16) __nv_bfloat16 g_Woh[(size_t)D_*D_];
__device__ __align__(16) __nv_bfloat16 g_Wol[(size_t)D_*D_];

// ---------------- helpers ----------------
__device__ __forceinline__ uint32_t smem_u32(const void* p) {
    uint32_t a;
    asm("{ .reg .u64 t; cvta.to.shared.u64 t, %1; cvt.u32.u64 %0, t; }" : "=r"(a) : "l"(p));
    return a;
}
#define SWZ128(o) ((o) ^ (((o) >> 3) & 0x70))

#define LDMX4(r0, r1, r2, r3, addr)                                           \
    asm volatile("ldmatrix.sync.aligned.m8n8.x4.shared.b16 {%0,%1,%2,%3}, [%4];" \
                 : "=r"(r0), "=r"(r1), "=r"(r2), "=r"(r3) : "r"(addr))
#define LDMX4T(r0, r1, r2, r3, addr)                                          \
    asm volatile("ldmatrix.sync.aligned.m8n8.x4.trans.shared.b16 {%0,%1,%2,%3}, [%4];" \
                 : "=r"(r0), "=r"(r1), "=r"(r2), "=r"(r3) : "r"(addr))

#define MMA16816(d, a, b0v, b1v)                                              \
    asm volatile("mma.sync.aligned.m16n8k16.row.col.f32.bf16.bf16.f32 "       \
                 "{%0,%1,%2,%3}, {%4,%5,%6,%7}, {%8,%9}, {%0,%1,%2,%3};"      \
                 : "+f"((d)[0]), "+f"((d)[1]), "+f"((d)[2]), "+f"((d)[3])     \
                 : "r"((a)[0]), "r"((a)[1]), "r"((a)[2]), "r"((a)[3]),        \
                   "r"(b0v), "r"(b1v))
// fp16 variant (for P@V single-term)
#define MMA16816H(d, a, b0v, b1v)                                             \
    asm volatile("mma.sync.aligned.m16n8k16.row.col.f32.f16.f16.f32 "         \
                 "{%0,%1,%2,%3}, {%4,%5,%6,%7}, {%8,%9}, {%0,%1,%2,%3};"      \
                 : "+f"((d)[0]), "+f"((d)[1]), "+f"((d)[2]), "+f"((d)[3])     \
                 : "r"((a)[0]), "r"((a)[1]), "r"((a)[2]), "r"((a)[3]),        \
                   "r"(b0v), "r"(b1v))

#define CP16(dst, src)                                                        \
    asm volatile("cp.async.cg.shared.global [%0], [%1], 16;" :: "r"(dst), "l"(src))
#define CP_COMMIT() asm volatile("cp.async.commit_group;" ::: "memory")
#define CP_WAIT(n)  asm volatile("cp.async.wait_group %0;" :: "n"(n) : "memory")

__device__ __forceinline__ uint32_t pack_bf16(float a, float b) {
    __nv_bfloat162 h = __floats2bfloat162_rn(a, b);
    return *(uint32_t*)&h;
}
__device__ __forceinline__ uint32_t pack_fp16(float a, float b) {
    __half2 h = __floats2half2_rn(a, b);
    return *(uint32_t*)&h;
}
// truncation hi/lo split: hi = top-16-bit truncation (PRMT), lo = bf16_rn(v-hi)
__device__ __forceinline__ void split2(float p0, float p1, uint32_t& hi, uint32_t& lo) {
    uint32_t u0 = __float_as_uint(p0), u1 = __float_as_uint(p1);
    hi = __byte_perm(u0, u1, 0x7632);
    float f0 = __uint_as_float(u0 & 0xFFFF0000u);
    float f1 = __uint_as_float(u1 & 0xFFFF0000u);
    lo = pack_bf16(p0 - f0, p1 - f1);
}

// ---------------- fused prep: x split + both weight transposes -------------
#define PREP_SPLIT_BLKS 8192
#define PREP_WQ_BLKS    3072
#define PREP_WO_BLKS    1024
__global__ __launch_bounds__(256) void prep_all(
    const float* __restrict__ x,
    __nv_bfloat16* __restrict__ Xh, __nv_bfloat16* __restrict__ Xl,
    const float* __restrict__ Wq,
    __nv_bfloat16* __restrict__ Wqh, __nv_bfloat16* __restrict__ Wql,
    const float* __restrict__ Wo,
    __nv_bfloat16* __restrict__ Woh, __nv_bfloat16* __restrict__ Wol)
{
    __shared__ float tile[32][33];
    const int bx = blockIdx.x, tid = threadIdx.x;
    if (bx < PREP_SPLIT_BLKS) {
        const int i = bx * 256 + tid;
        float4 v = ((const float4*)x)[i];
        uint2 Hu, Lu;
        split2(v.x, v.y, Hu.x, Lu.x);
        split2(v.z, v.w, Hu.y, Lu.y);
        ((uint2*)Xh)[i] = Hu;
        ((uint2*)Xl)[i] = Lu;
        return;
    }
    const float* W; __nv_bfloat16 *Th, *Tl; int N, idx;
    if (bx < PREP_SPLIT_BLKS + PREP_WQ_BLKS) {
        idx = bx - PREP_SPLIT_BLKS; W = Wq; Th = Wqh; Tl = Wql; N = 3 * D_;
    } else {
        idx = bx - PREP_SPLIT_BLKS - PREP_WQ_BLKS; W = Wo; Th = Woh; Tl = Wol; N = D_;
    }
    const int nblk = N / 32;
    const int n0 = (idx % nblk) * 32, k0 = (idx / nblk) * 32;
    const int tx = tid & 31, ty = tid >> 5;
#pragma unroll
    for (int i = 0; i < 4; i++)
        tile[ty + 8 * i][tx] = W[(size_t)(k0 + ty + 8 * i) * N + n0 + tx];
    __syncthreads();
#pragma unroll
    for (int i = 0; i < 4; i++) {
        float v = tile[tx][ty + 8 * i];
        __nv_bfloat16 h = __float2bfloat16(v);
        size_t o = (size_t)(n0 + ty + 8 * i) * GK + k0 + tx;
        Th[o] = h;
        Tl[o] = __float2bfloat16(v - __bfloat162float(h));
    }
}

// ---------------- mma GEMM (R11 core; V written as fp16 in mode 1) ---------
#define GSTG_B 32768
#define GSM_TOT (3 * GSTG_B)
__global__ __launch_bounds__(256, 2) void gemm_mma(
    const __nv_bfloat16* __restrict__ Ah, const __nv_bfloat16* __restrict__ Al,
    const __nv_bfloat16* __restrict__ Bh, const __nv_bfloat16* __restrict__ Bl,
    const float* __restrict__ bias, float* __restrict__ Cf,
    __nv_bfloat16* __restrict__ oQh, __nv_bfloat16* __restrict__ oQl,
    __nv_bfloat16* __restrict__ oKh, __nv_bfloat16* __restrict__ oKl,
    __half* __restrict__ oVf,
    int N, int mode)
{
    extern __shared__ char smem[];
    const uint32_t sb = smem_u32(smem);
    const int tid = threadIdx.x, lane = tid & 31, wid = tid >> 5;
    const int wm = (wid & 1) * 64, wn = (wid >> 1) * 32;
    const int m0 = blockIdx.y * 128, n0 = blockIdx.x * 128;

    float acc[4][4][4];
#pragma unroll
    for (int i = 0; i < 4; i++)
#pragma unroll
        for (int j = 0; j < 4; j++)
#pragma unroll
            for (int k = 0; k < 4; k++) acc[i][j][k] = 0.f;

    const int lr = tid >> 3, lseg = tid & 7;
    const int a_row = wm + (lane & 15), a_k16 = lane >> 4;
    const int b_row = wn + (lane & 7) + ((lane & 16) >> 1), b_k16 = (lane >> 3) & 1;

    auto issue = [&](int c, int st) {
        const int kb = c * 32;
        const uint32_t stb = sb + st * GSTG_B;
#pragma unroll
        for (int it = 0; it < 4; it++) {
            const int r = lr + 32 * it;
            const uint32_t so = SWZ128((uint32_t)(r * 128 + lseg * 16));
            const __nv_bfloat16* src = (lseg < 4)
                ? Ah + (size_t)(m0 + r) * GK + kb + lseg * 8
                : Al + (size_t)(m0 + r) * GK + kb + (lseg - 4) * 8;
            CP16(stb + so, src);
        }
#pragma unroll
        for (int it = 0; it < 4; it++) {
            const int r = lr + 32 * it;
            const uint32_t so = SWZ128((uint32_t)(r * 128 + lseg * 16));
            const __nv_bfloat16* src = (lseg < 4)
                ? Bh + (size_t)(n0 + r) * GK + kb + lseg * 8
                : Bl + (size_t)(n0 + r) * GK + kb + (lseg - 4) * 8;
            CP16(stb + 16384 + so, src);
        }
        CP_COMMIT();
    };

    issue(0, 0);
    issue(1, 1);
    for (int c = 0; c < 32; c++) {
        if (c + 1 < 32) CP_WAIT(1); else CP_WAIT(0);
        __syncthreads();
        if (c + 2 < 32) issue(c + 2, (c + 2) % 3);
        const uint32_t sA = sb + (c % 3) * GSTG_B;
        const uint32_t sB = sA + 16384;
#pragma unroll
        for (int kk = 0; kk < 2; kk++) {
            const uint32_t hA = kk * 32 + a_k16 * 16;
            const uint32_t hB = kk * 32 + b_k16 * 16;
            uint32_t bh[2][4], bl[2][4];
#pragma unroll
            for (int nj = 0; nj < 2; nj++) {
                const uint32_t base = (uint32_t)((b_row + nj * 16) * 128);
                LDMX4(bh[nj][0], bh[nj][1], bh[nj][2], bh[nj][3], sB + SWZ128(base + hB));
                LDMX4(bl[nj][0], bl[nj][1], bl[nj][2], bl[nj][3], sB + SWZ128(base + 64 + hB));
            }
#pragma unroll
            for (int mi = 0; mi < 4; mi++) {
                const uint32_t base = (uint32_t)((a_row + mi * 16) * 128);
                uint32_t ah[4], al[4];
                LDMX4(ah[0], ah[1], ah[2], ah[3], sA + SWZ128(base + hA));
                LDMX4(al[0], al[1], al[2], al[3], sA + SWZ128(base + 64 + hA));
#pragma unroll
                for (int nj = 0; nj < 2; nj++)
#pragma unroll
                    for (int q = 0; q < 2; q++)
                        MMA16816(acc[mi][nj * 2 + q], ah, bh[nj][q * 2], bh[nj][q * 2 + 1]);
#pragma unroll
                for (int nj = 0; nj < 2; nj++)
#pragma unroll
                    for (int q = 0; q < 2; q++)
                        MMA16816(acc[mi][nj * 2 + q], al, bh[nj][q * 2], bh[nj][q * 2 + 1]);
#pragma unroll
                for (int nj = 0; nj < 2; nj++)
#pragma unroll
                    for (int q = 0; q < 2; q++)
                        MMA16816(acc[mi][nj * 2 + q], ah, bl[nj][q * 2], bl[nj][q * 2 + 1]);
            }
        }
    }

    const int rl = lane >> 2, cl = (lane & 3) * 2;
#pragma unroll
    for (int mi = 0; mi < 4; mi++) {
        const int r_base = wm + mi * 16 + rl;
#pragma unroll
        for (int ni = 0; ni < 4; ni++) {
            const int cn = wn + ni * 8 + cl;
            const float2 b2 = *(const float2*)&bias[n0 + cn];
#pragma unroll
            for (int half = 0; half < 2; half++) {
                const int m = m0 + r_base + half * 8;
                float v0 = acc[mi][ni][half * 2 + 0] + b2.x;
                float v1 = acc[mi][ni][half * 2 + 1] + b2.y;
                if (mode == 0) {
                    float2 v; v.x = v0; v.y = v1;
                    *(float2*)&Cf[(size_t)m * N + n0 + cn] = v;
                } else {
                    const int b = m >> 11, t = m & 2047;
                    const int part = n0 >> 10;
                    const int d = (n0 & 1023) + cn;
                    const int h = d >> 6, dk = d & 63;
                    const size_t off = (((size_t)(b * H_ + h)) * T_ + t) * DK_ + dk;
                    if (part == 2) {
                        *(uint32_t*)(oVf + off) = pack_fp16(v0, v1);
                    } else {
                        uint32_t hp, lw;
                        split2(v0, v1, hp, lw);
                        __nv_bfloat16 *dh = (part == 0) ? oQh : oKh;
                        __nv_bfloat16 *dl = (part == 0) ? oQl : oKl;
                        *(uint32_t*)(dh + off) = hp;
                        *(uint32_t*)(dl + off) = lw;
                    }
                }
            }
        }
    }
}

// ---------------- mma.sync flash attention: QK 3-term bf16, PV fp16 single -
// smem: Q hi/lo 32KB; 3 KV stages of 48KB (KH 16K | KL 16K | Vf 16K)
#define ASM_QH 0
#define ASM_QL 16384
#define ASM_KV 32768
#define AKV_ST 49152
#define AKV_KH 0
#define AKV_KL 16384
#define AKV_VF 32768
#define ASM_TOT (32768 + 3 * AKV_ST)   // 180224 B

__global__ __launch_bounds__(256, 1) void attn_mma(
    const __nv_bfloat16* __restrict__ Qh, const __nv_bfloat16* __restrict__ Ql,
    const __nv_bfloat16* __restrict__ Kh, const __nv_bfloat16* __restrict__ Kl,
    const __half* __restrict__ Vf,
    __nv_bfloat16* __restrict__ Ah, __nv_bfloat16* __restrict__ Al)
{
    extern __shared__ char smem[];
    const uint32_t sb = smem_u32(smem);
    const int tid = threadIdx.x, lane = tid & 31, wid = tid >> 5;
    const int qt = gridDim.x - 1 - blockIdx.x;
    const int q0 = qt * 128;
    const int h = blockIdx.y, b = blockIdx.z;
    const size_t hb = ((size_t)(b * H_ + h)) * T_ * DK_;

    {   // Q tile (group 0)
#pragma unroll
        for (int it = 0; it < 4; it++) {
            const int u = tid + 256 * it;
            const int r = u >> 3, seg = u & 7;
            const uint32_t so = SWZ128((uint32_t)(r * 128 + seg * 16));
            const size_t g = hb + (size_t)(q0 + r) * DK_ + seg * 8;
            CP16(sb + ASM_QH + so, Qh + g);
            CP16(sb + ASM_QL + so, Ql + g);
        }
        CP_COMMIT();
    }

    auto issueKV = [&](int kt, int st) {
        const int k0 = kt * 128;
        const uint32_t stb = sb + ASM_KV + st * AKV_ST;
#pragma unroll
        for (int it = 0; it < 4; it++) {
            const int u = tid + 256 * it;
            const int r = u >> 3, seg = u & 7;
            const uint32_t so = SWZ128((uint32_t)(r * 128 + seg * 16));
            const size_t g = hb + (size_t)(k0 + r) * DK_ + seg * 8;
            CP16(stb + AKV_KH + so, Kh + g);
            CP16(stb + AKV_KL + so, Kl + g);
            CP16(stb + AKV_VF + so, Vf + g);
        }
        CP_COMMIT();
    };

    const int nkt = qt;
    issueKV(0, 0);
    if (nkt >= 1) { issueKV(1, 1); CP_WAIT(2); }
    else          { CP_WAIT(1); }
    __syncthreads();

    const int a_row = wid * 16 + (lane & 15), a_k16 = lane >> 4;
    uint32_t qfh[4][4], qfl[4][4];
#pragma unroll
    for (int kk = 0; kk < 4; kk++) {
        const uint32_t off = SWZ128((uint32_t)(a_row * 128 + kk * 32 + a_k16 * 16));
        LDMX4(qfh[kk][0], qfh[kk][1], qfh[kk][2], qfh[kk][3], sb + ASM_QH + off);
        LDMX4(qfl[kk][0], qfl[kk][1], qfl[kk][2], qfl[kk][3], sb + ASM_QL + off);
    }

    const int b_row = (lane & 7) + ((lane & 16) >> 1), b_k16 = (lane >> 3) & 1;
    const int vm = lane >> 3, vr = lane & 7;
    const int rr = lane >> 2, t2 = (lane & 3) * 2;

    float o[8][4];
#pragma unroll
    for (int i = 0; i < 8; i++)
#pragma unroll
        for (int j = 0; j < 4; j++) o[i][j] = 0.f;
    float m_r = -1e30f, m_r8 = -1e30f, l_r = 0.f, l_r8 = 0.f;

    for (int kt = 0; kt <= nkt; kt++) {
        if (kt + 1 <= nkt) CP_WAIT(1); else CP_WAIT(0);
        __syncthreads();
        if (kt + 2 <= nkt) issueKV(kt + 2, (kt + 2) % 3);
        const uint32_t stb = sb + ASM_KV + (kt % 3) * AKV_ST;
        const int k0 = kt * 128;

        float s[16][4];
#pragma unroll
        for (int i = 0; i < 16; i++)
#pragma unroll
            for (int j = 0; j < 4; j++) s[i][j] = 0.f;
#pragma unroll
        for (int kk = 0; kk < 4; kk++) {
#pragma unroll
            for (int nn = 0; nn < 8; nn++) {
                const uint32_t off = SWZ128((uint32_t)((nn * 16 + b_row) * 128 + kk * 32 + b_k16 * 16));
                uint32_t kh[4], kl[4];
                LDMX4(kh[0], kh[1], kh[2], kh[3], stb + AKV_KH + off);
                LDMX4(kl[0], kl[1], kl[2], kl[3], stb + AKV_KL + off);
                float* s0 = s[2 * nn];
                float* s1 = s[2 * nn + 1];
                MMA16816(s0, qfh[kk], kh[0], kh[1]);
                MMA16816(s0, qfl[kk], kh[0], kh[1]);
                MMA16816(s0, qfh[kk], kl[0], kl[1]);
                MMA16816(s1, qfh[kk], kh[2], kh[3]);
                MMA16816(s1, qfl[kk], kh[2], kh[3]);
                MMA16816(s1, qfh[kk], kl[2], kl[3]);
            }
        }

        const bool diag = (k0 == q0);
        const int qi_r = q0 + wid * 16 + rr;
#pragma unroll
        for (int ni = 0; ni < 16; ni++) {
            const int kc = k0 + ni * 8 + t2;
#pragma unroll
            for (int e = 0; e < 4; e++) {
                float v = s[ni][e] * 0.125f;
                if (diag) {
                    const int kj = kc + (e & 1);
                    const int qi = qi_r + ((e >> 1) << 3);
                    if (kj > qi) v = -1e30f;
                }
                s[ni][e] = v;
            }
        }

        float rmr = -1e30f, rm8 = -1e30f;
#pragma unroll
        for (int ni = 0; ni < 16; ni++) {
            rmr = fmaxf(rmr, fmaxf(s[ni][0], s[ni][1]));
            rm8 = fmaxf(rm8, fmaxf(s[ni][2], s[ni][3]));
        }
        rmr = fmaxf(rmr, __shfl_xor_sync(0xffffffffu, rmr, 1));
        rmr = fmaxf(rmr, __shfl_xor_sync(0xffffffffu, rmr, 2));
        rm8 = fmaxf(rm8, __shfl_xor_sync(0xffffffffu, rm8, 1));
        rm8 = fmaxf(rm8, __shfl_xor_sync(0xffffffffu, rm8, 2));

        const float mnr = fmaxf(m_r, rmr), mn8 = fmaxf(m_r8, rm8);
        const float ar = __expf(m_r - mnr), a8 = __expf(m_r8 - mn8);
        m_r = mnr; m_r8 = mn8;
        l_r *= ar; l_r8 *= a8;
#pragma unroll
        for (int dn = 0; dn < 8; dn++) {
            o[dn][0] *= ar; o[dn][1] *= ar; o[dn][2] *= a8; o[dn][3] *= a8;
        }

        // P = exp(S-m) as fp16; O += P@V (single term, fp16 MMA)
#pragma unroll
        for (int kk = 0; kk < 8; kk++) {
            float p0 = __expf(s[2 * kk][0] - m_r);
            float p1 = __expf(s[2 * kk][1] - m_r);
            float p2 = __expf(s[2 * kk][2] - m_r8);
            float p3 = __expf(s[2 * kk][3] - m_r8);
            float p4 = __expf(s[2 * kk + 1][0] - m_r);
            float p5 = __expf(s[2 * kk + 1][1] - m_r);
            float p6 = __expf(s[2 * kk + 1][2] - m_r8);
            float p7 = __expf(s[2 * kk + 1][3] - m_r8);
            l_r  += p0 + p1 + p4 + p5;
            l_r8 += p2 + p3 + p6 + p7;

            uint32_t pH[4];
            pH[0] = pack_fp16(p0, p1);
            pH[1] = pack_fp16(p2, p3);
            pH[2] = pack_fp16(p4, p5);
            pH[3] = pack_fp16(p6, p7);
#pragma unroll
            for (int dp = 0; dp < 4; dp++) {
                const uint32_t off = SWZ128((uint32_t)(
                    (kk * 16 + (vm & 1) * 8 + vr) * 128 + (vm >> 1) * 16 + dp * 32));
                uint32_t vh[4];
                LDMX4T(vh[0], vh[1], vh[2], vh[3], stb + AKV_VF + off);
                MMA16816H(o[2 * dp], pH, vh[0], vh[1]);
                MMA16816H(o[2 * dp + 1], pH, vh[2], vh[3]);
            }
        }
    }

    l_r  += __shfl_xor_sync(0xffffffffu, l_r, 1);
    l_r  += __shfl_xor_sync(0xffffffffu, l_r, 2);
    l_r8 += __shfl_xor_sync(0xffffffffu, l_r8, 1);
    l_r8 += __shfl_xor_sync(0xffffffffu, l_r8, 2);
    const float ir = 1.f / l_r, i8 = 1.f / l_r8;
    const int trow = q0 + wid * 16 + rr;
#pragma unroll
    for (int dn = 0; dn < 8; dn++) {
        float v0 = o[dn][0] * ir, v1 = o[dn][1] * ir;
        float v2 = o[dn][2] * i8, v3 = o[dn][3] * i8;
        const int col = h * DK_ + dn * 8 + t2;
        size_t o1 = ((size_t)(b * T_ + trow)) * D_ + col;
        size_t o2 = ((size_t)(b * T_ + trow + 8)) * D_ + col;
        uint32_t hp, lw;
        split2(v0, v1, hp, lw);
        *(uint32_t*)(Ah + o1) = hp; *(uint32_t*)(Al + o1) = lw;
        split2(v2, v3, hp, lw);
        *(uint32_t*)(Ah + o2) = hp; *(uint32_t*)(Al + o2) = lw;
    }
}

// ---------------------------------------------------------------------------
extern "C" void kernel_launch(void* const* d_in, const int* in_sizes, int n_in,
                              void* d_out, int out_size)
{
    const float* x     = (const float*)d_in[0];
    const float* W_qkv = (const float*)d_in[1];
    const float* b_qkv = (const float*)d_in[2];
    const float* W_o   = (const float*)d_in[3];
    const float* b_o   = (const float*)d_in[4];

    __nv_bfloat16 *Qh, *Ql, *Kh, *Kl, *Xh, *Xl, *Ahp, *Alp, *Wqh, *Wql, *Woh, *Wol;
    __half *Vf;
    cudaGetSymbolAddress((void**)&Qh, g_Qh); cudaGetSymbolAddress((void**)&Ql, g_Ql);
    cudaGetSymbolAddress((void**)&Kh, g_Kh); cudaGetSymbolAddress((void**)&Kl, g_Kl);
    cudaGetSymbolAddress((void**)&Vf, g_Vf);
    cudaGetSymbolAddress((void**)&Xh, g_Xh); cudaGetSymbolAddress((void**)&Xl, g_Xl);
    cudaGetSymbolAddress((void**)&Ahp, g_Ah); cudaGetSymbolAddress((void**)&Alp, g_Al);
    cudaGetSymbolAddress((void**)&Wqh, g_Wqh); cudaGetSymbolAddress((void**)&Wql, g_Wql);
    cudaGetSymbolAddress((void**)&Woh, g_Woh); cudaGetSymbolAddress((void**)&Wol, g_Wol);

    const int M = B_ * T_;

    prep_all<<<PREP_SPLIT_BLKS + PREP_WQ_BLKS + PREP_WO_BLKS, 256>>>(
        x, Xh, Xl, W_qkv, Wqh, Wql, W_o, Woh, Wol);

    cudaFuncSetAttribute(gemm_mma, cudaFuncAttributeMaxDynamicSharedMemorySize, GSM_TOT);
    cudaFuncSetAttribute(attn_mma, cudaFuncAttributeMaxDynamicSharedMemorySize, ASM_TOT);

    // 1) QKV projection -> Q/K bf16 hi/lo + V fp16, head-major
    {
        dim3 grid(3 * D_ / 128, M / 128);
        gemm_mma<<<grid, 256, GSM_TOT>>>(Xh, Xl, Wqh, Wql, b_qkv, nullptr,
                                         Qh, Ql, Kh, Kl, Vf, 3 * D_, 1);
    }

    // 2) causal flash attention -> Ah/Al bf16 hi/lo
    {
        dim3 grid(T_ / 128, H_, B_);
        attn_mma<<<grid, 256, ASM_TOT>>>(Qh, Ql, Kh, Kl, Vf, Ahp, Alp);
    }

    // 3) output projection -> fp32 d_out
    {
        dim3 grid(D_ / 128, M / 128);
        gemm_mma<<<grid, 256, GSM_TOT>>>(Ahp, Alp, Woh, Wol, b_o, (float*)d_out,
                                         nullptr, nullptr, nullptr, nullptr, nullptr,
                                         D_, 0);
    }
}

// round 17
// speedup vs baseline: 1.8480x; 1.0814x over previous
#include <cuda_runtime.h>
#include <cuda_bf16.h>
#include <cuda_fp16.h>
#include <cstdint>

#define B_  4
#define T_  2048
#define H_  16
#define DK_ 64
#define D_  1024
#define GK  1024

// ---------------- scratch (device globals; allocation-free) ----------------
__device__ __align__(16) __nv_bfloat16 g_Qh[(size_t)B_*H_*T_*DK_];
__device__ __align__(16) __nv_bfloat16 g_Ql[(size_t)B_*H_*T_*DK_];
__device__ __align__(16) __nv_bfloat16 g_Kh[(size_t)B_*H_*T_*DK_];
__device__ __align__(16) __nv_bfloat16 g_Kl[(size_t)B_*H_*T_*DK_];
__device__ __align__(16) __half        g_Vf[(size_t)B_*H_*T_*DK_];
__device__ __align__(16) __nv_bfloat16 g_Xh[(size_t)B_*T_*D_];      // x bf16 hi/lo (QK proj)
__device__ __align__(16) __nv_bfloat16 g_Xl[(size_t)B_*T_*D_];
__device__ __align__(16) __half        g_Xfh[(size_t)B_*T_*D_];     // x fp16 hi/lo (V proj)
__device__ __align__(16) __half        g_Xfl[(size_t)B_*T_*D_];
__device__ __align__(16) __half        g_Afh[(size_t)B_*T_*D_];     // attn out fp16 hi/lo
__device__ __align__(16) __half        g_Afl[(size_t)B_*T_*D_];
__device__ __align__(16) __nv_bfloat16 g_Wqh[(size_t)2*D_*D_];      // W_qk bf16 hi/lo [2048][1024]
__device__ __align__(16) __nv_bfloat16 g_Wql[(size_t)2*D_*D_];
__device__ __align__(16) __half        g_Wvf[(size_t)D_*D_];        // W_v fp16 [1024][1024]
__device__ __align__(16) __half        g_Wof[(size_t)D_*D_];        // W_o fp16 [1024][1024]

// ---------------- helpers ----------------
__device__ __forceinline__ uint32_t smem_u32(const void* p) {
    uint32_t a;
    asm("{ .reg .u64 t; cvta.to.shared.u64 t, %1; cvt.u32.u64 %0, t; }" : "=r"(a) : "l"(p));
    return a;
}
#define SWZ128(o) ((o) ^ (((o) >> 3) & 0x70))

#define LDMX4(r0, r1, r2, r3, addr)                                           \
    asm volatile("ldmatrix.sync.aligned.m8n8.x4.shared.b16 {%0,%1,%2,%3}, [%4];" \
                 : "=r"(r0), "=r"(r1), "=r"(r2), "=r"(r3) : "r"(addr))
#define LDMX4T(r0, r1, r2, r3, addr)                                          \
    asm volatile("ldmatrix.sync.aligned.m8n8.x4.trans.shared.b16 {%0,%1,%2,%3}, [%4];" \
                 : "=r"(r0), "=r"(r1), "=r"(r2), "=r"(r3) : "r"(addr))

#define MMA16816(d, a, b0v, b1v)                                              \
    asm volatile("mma.sync.aligned.m16n8k16.row.col.f32.bf16.bf16.f32 "       \
                 "{%0,%1,%2,%3}, {%4,%5,%6,%7}, {%8,%9}, {%0,%1,%2,%3};"      \
                 : "+f"((d)[0]), "+f"((d)[1]), "+f"((d)[2]), "+f"((d)[3])     \
                 : "r"((a)[0]), "r"((a)[1]), "r"((a)[2]), "r"((a)[3]),        \
                   "r"(b0v), "r"(b1v))
#define MMA16816H(d, a, b0v, b1v)                                             \
    asm volatile("mma.sync.aligned.m16n8k16.row.col.f32.f16.f16.f32 "         \
                 "{%0,%1,%2,%3}, {%4,%5,%6,%7}, {%8,%9}, {%0,%1,%2,%3};"      \
                 : "+f"((d)[0]), "+f"((d)[1]), "+f"((d)[2]), "+f"((d)[3])     \
                 : "r"((a)[0]), "r"((a)[1]), "r"((a)[2]), "r"((a)[3]),        \
                   "r"(b0v), "r"(b1v))

#define CP16(dst, src)                                                        \
    asm volatile("cp.async.cg.shared.global [%0], [%1], 16;" :: "r"(dst), "l"(src))
#define CP_COMMIT() asm volatile("cp.async.commit_group;" ::: "memory")
#define CP_WAIT(n)  asm volatile("cp.async.wait_group %0;" :: "n"(n) : "memory")

__device__ __forceinline__ uint32_t pack_bf16(float a, float b) {
    __nv_bfloat162 h = __floats2bfloat162_rn(a, b);
    return *(uint32_t*)&h;
}
__device__ __forceinline__ uint32_t pack_fp16(float a, float b) {
    __half2 h = __floats2half2_rn(a, b);
    return *(uint32_t*)&h;
}
// bf16 truncation hi/lo split
__device__ __forceinline__ void split2(float p0, float p1, uint32_t& hi, uint32_t& lo) {
    uint32_t u0 = __float_as_uint(p0), u1 = __float_as_uint(p1);
    hi = __byte_perm(u0, u1, 0x7632);
    float f0 = __uint_as_float(u0 & 0xFFFF0000u);
    float f1 = __uint_as_float(u1 & 0xFFFF0000u);
    lo = pack_bf16(p0 - f0, p1 - f1);
}
// fp16 hi/lo split (hi = rn(v), lo = rn(v - hi))
__device__ __forceinline__ void split2h(float p0, float p1, uint32_t& hi, uint32_t& lo) {
    __half h0 = __float2half_rn(p0), h1 = __float2half_rn(p1);
    __half2 hp; hp.x = h0; hp.y = h1;
    hi = *(uint32_t*)&hp;
    lo = pack_fp16(p0 - __half2float(h0), p1 - __half2float(h1));
}

// ---------------- fused prep ----------------
// [0,8192): x -> bf16 hi/lo + fp16 hi/lo
// [8192,10240): W_qk bf16 hi/lo transpose (cols 0..2047)
// [10240,11264): W_v fp16 transpose (cols 2048..3071)
// [11264,12288): W_o fp16 transpose
#define PREP_SPLIT_BLKS 8192
#define PREP_WQK_BLKS   2048
#define PREP_WV_BLKS    1024
#define PREP_WO_BLKS    1024
__global__ __launch_bounds__(256) void prep_all(
    const float* __restrict__ x,
    __nv_bfloat16* __restrict__ Xh, __nv_bfloat16* __restrict__ Xl,
    __half* __restrict__ Xfh, __half* __restrict__ Xfl,
    const float* __restrict__ Wq,
    __nv_bfloat16* __restrict__ Wqh, __nv_bfloat16* __restrict__ Wql,
    __half* __restrict__ Wvf,
    const float* __restrict__ Wo, __half* __restrict__ Wof)
{
    __shared__ float tile[32][33];
    const int bx = blockIdx.x, tid = threadIdx.x;
    if (bx < PREP_SPLIT_BLKS) {
        const int i = bx * 256 + tid;
        float4 v = ((const float4*)x)[i];
        uint2 Hu, Lu, Fh, Fl;
        split2(v.x, v.y, Hu.x, Lu.x);
        split2(v.z, v.w, Hu.y, Lu.y);
        split2h(v.x, v.y, Fh.x, Fl.x);
        split2h(v.z, v.w, Fh.y, Fl.y);
        ((uint2*)Xh)[i] = Hu;  ((uint2*)Xl)[i] = Lu;
        ((uint2*)Xfh)[i] = Fh; ((uint2*)Xfl)[i] = Fl;
        return;
    }
    const int tx = tid & 31, ty = tid >> 5;
    if (bx < PREP_SPLIT_BLKS + PREP_WQK_BLKS) {
        const int idx = bx - PREP_SPLIT_BLKS;
        const int nblk = (2 * D_) / 32;
        const int n0 = (idx % nblk) * 32, k0 = (idx / nblk) * 32;
#pragma unroll
        for (int i = 0; i < 4; i++)
            tile[ty + 8 * i][tx] = Wq[(size_t)(k0 + ty + 8 * i) * (3 * D_) + n0 + tx];
        __syncthreads();
#pragma unroll
        for (int i = 0; i < 4; i++) {
            float v = tile[tx][ty + 8 * i];
            __nv_bfloat16 h = __float2bfloat16(v);
            size_t o = (size_t)(n0 + ty + 8 * i) * GK + k0 + tx;
            Wqh[o] = h;
            Wql[o] = __float2bfloat16(v - __bfloat162float(h));
        }
        return;
    }
    const float* W; __half* Tf; int coff, idx;
    if (bx < PREP_SPLIT_BLKS + PREP_WQK_BLKS + PREP_WV_BLKS) {
        idx = bx - PREP_SPLIT_BLKS - PREP_WQK_BLKS; W = Wq; Tf = Wvf; coff = 2 * D_;
    } else {
        idx = bx - PREP_SPLIT_BLKS - PREP_WQK_BLKS - PREP_WV_BLKS; W = Wo; Tf = Wof; coff = 0;
    }
    const int srcN = (coff != 0) ? 3 * D_ : D_;
    const int nblk = D_ / 32;
    const int n0 = (idx % nblk) * 32, k0 = (idx / nblk) * 32;
#pragma unroll
    for (int i = 0; i < 4; i++)
        tile[ty + 8 * i][tx] = W[(size_t)(k0 + ty + 8 * i) * srcN + coff + n0 + tx];
    __syncthreads();
#pragma unroll
    for (int i = 0; i < 4; i++) {
        size_t o = (size_t)(n0 + ty + 8 * i) * GK + k0 + tx;
        Tf[o] = __float2half_rn(tile[tx][ty + 8 * i]);
    }
}

// ---------------- 3-term bf16 GEMM (R16 core) — QK projection only ---------
#define GSTG_B 32768
#define GSM_TOT (3 * GSTG_B)
__global__ __launch_bounds__(256, 2) void gemm_mma(
    const __nv_bfloat16* __restrict__ Ah, const __nv_bfloat16* __restrict__ Al,
    const __nv_bfloat16* __restrict__ Bh, const __nv_bfloat16* __restrict__ Bl,
    const float* __restrict__ bias,
    __nv_bfloat16* __restrict__ oQh, __nv_bfloat16* __restrict__ oQl,
    __nv_bfloat16* __restrict__ oKh, __nv_bfloat16* __restrict__ oKl)
{
    extern __shared__ char smem[];
    const uint32_t sb = smem_u32(smem);
    const int tid = threadIdx.x, lane = tid & 31, wid = tid >> 5;
    const int wm = (wid & 1) * 64, wn = (wid >> 1) * 32;
    const int m0 = blockIdx.y * 128, n0 = blockIdx.x * 128;

    float acc[4][4][4];
#pragma unroll
    for (int i = 0; i < 4; i++)
#pragma unroll
        for (int j = 0; j < 4; j++)
#pragma unroll
            for (int k = 0; k < 4; k++) acc[i][j][k] = 0.f;

    const int lr = tid >> 3, lseg = tid & 7;
    const int a_row = wm + (lane & 15), a_k16 = lane >> 4;
    const int b_row = wn + (lane & 7) + ((lane & 16) >> 1), b_k16 = (lane >> 3) & 1;

    auto issue = [&](int c, int st) {
        const int kb = c * 32;
        const uint32_t stb = sb + st * GSTG_B;
#pragma unroll
        for (int it = 0; it < 4; it++) {
            const int r = lr + 32 * it;
            const uint32_t so = SWZ128((uint32_t)(r * 128 + lseg * 16));
            const __nv_bfloat16* src = (lseg < 4)
                ? Ah + (size_t)(m0 + r) * GK + kb + lseg * 8
                : Al + (size_t)(m0 + r) * GK + kb + (lseg - 4) * 8;
            CP16(stb + so, src);
        }
#pragma unroll
        for (int it = 0; it < 4; it++) {
            const int r = lr + 32 * it;
            const uint32_t so = SWZ128((uint32_t)(r * 128 + lseg * 16));
            const __nv_bfloat16* src = (lseg < 4)
                ? Bh + (size_t)(n0 + r) * GK + kb + lseg * 8
                : Bl + (size_t)(n0 + r) * GK + kb + (lseg - 4) * 8;
            CP16(stb + 16384 + so, src);
        }
        CP_COMMIT();
    };

    issue(0, 0);
    issue(1, 1);
    for (int c = 0; c < 32; c++) {
        if (c + 1 < 32) CP_WAIT(1); else CP_WAIT(0);
        __syncthreads();
        if (c + 2 < 32) issue(c + 2, (c + 2) % 3);
        const uint32_t sA = sb + (c % 3) * GSTG_B;
        const uint32_t sB = sA + 16384;
#pragma unroll
        for (int kk = 0; kk < 2; kk++) {
            const uint32_t hA = kk * 32 + a_k16 * 16;
            const uint32_t hB = kk * 32 + b_k16 * 16;
            uint32_t bh[2][4], bl[2][4];
#pragma unroll
            for (int nj = 0; nj < 2; nj++) {
                const uint32_t base = (uint32_t)((b_row + nj * 16) * 128);
                LDMX4(bh[nj][0], bh[nj][1], bh[nj][2], bh[nj][3], sB + SWZ128(base + hB));
                LDMX4(bl[nj][0], bl[nj][1], bl[nj][2], bl[nj][3], sB + SWZ128(base + 64 + hB));
            }
#pragma unroll
            for (int mi = 0; mi < 4; mi++) {
                const uint32_t base = (uint32_t)((a_row + mi * 16) * 128);
                uint32_t ah[4], al[4];
                LDMX4(ah[0], ah[1], ah[2], ah[3], sA + SWZ128(base + hA));
                LDMX4(al[0], al[1], al[2], al[3], sA + SWZ128(base + 64 + hA));
#pragma unroll
                for (int nj = 0; nj < 2; nj++)
#pragma unroll
                    for (int q = 0; q < 2; q++)
                        MMA16816(acc[mi][nj * 2 + q], ah, bh[nj][q * 2], bh[nj][q * 2 + 1]);
#pragma unroll
                for (int nj = 0; nj < 2; nj++)
#pragma unroll
                    for (int q = 0; q < 2; q++)
                        MMA16816(acc[mi][nj * 2 + q], al, bh[nj][q * 2], bh[nj][q * 2 + 1]);
#pragma unroll
                for (int nj = 0; nj < 2; nj++)
#pragma unroll
                    for (int q = 0; q < 2; q++)
                        MMA16816(acc[mi][nj * 2 + q], ah, bl[nj][q * 2], bl[nj][q * 2 + 1]);
            }
        }
    }

    const int rl = lane >> 2, cl = (lane & 3) * 2;
#pragma unroll
    for (int mi = 0; mi < 4; mi++) {
        const int r_base = wm + mi * 16 + rl;
#pragma unroll
        for (int ni = 0; ni < 4; ni++) {
            const int cn = wn + ni * 8 + cl;
            const float2 b2 = *(const float2*)&bias[n0 + cn];
#pragma unroll
            for (int half = 0; half < 2; half++) {
                const int m = m0 + r_base + half * 8;
                float v0 = acc[mi][ni][half * 2 + 0] + b2.x;
                float v1 = acc[mi][ni][half * 2 + 1] + b2.y;
                const int b = m >> 11, t = m & 2047;
                const int part = n0 >> 10;              // 0=Q 1=K
                const int d = (n0 & 1023) + cn;
                const int h = d >> 6, dk = d & 63;
                uint32_t hp, lw;
                split2(v0, v1, hp, lw);
                const size_t off = (((size_t)(b * H_ + h)) * T_ + t) * DK_ + dk;
                __nv_bfloat16 *dh = (part == 0) ? oQh : oKh;
                __nv_bfloat16 *dl = (part == 0) ? oQl : oKl;
                *(uint32_t*)(dh + off) = hp;
                *(uint32_t*)(dl + off) = lw;
            }
        }
    }
}

// ---------------- 2-term fp16 GEMM: C = (Ah+Al) @ B^T + bias ---------------
// A fp16 hi/lo [M][1024]; B fp16 [N][1024]. K-chunk 64; stage Ah16K|Al16K|B16K
// mode 0: fp32 out. mode 1: head-scatter fp16 (V projection).
#define G2_ST 49152
#define G2_TOT (3 * G2_ST)   // 144 KB
__global__ __launch_bounds__(256) void gemm_2t(
    const __half* __restrict__ Ah, const __half* __restrict__ Al,
    const __half* __restrict__ Bf,
    const float* __restrict__ bias, float* __restrict__ Cf,
    __half* __restrict__ oVf, int N, int mode)
{
    extern __shared__ char smem[];
    const uint32_t sb = smem_u32(smem);
    const int tid = threadIdx.x, lane = tid & 31, wid = tid >> 5;
    const int wm = (wid & 1) * 64, wn = (wid >> 1) * 32;
    const int m0 = blockIdx.y * 128, n0 = blockIdx.x * 128;

    float acc[4][4][4];
#pragma unroll
    for (int i = 0; i < 4; i++)
#pragma unroll
        for (int j = 0; j < 4; j++)
#pragma unroll
            for (int k = 0; k < 4; k++) acc[i][j][k] = 0.f;

    const int lr = tid >> 3, lseg = tid & 7;
    const int a_row = wm + (lane & 15), a_k16 = lane >> 4;
    const int b_row = wn + (lane & 7) + ((lane & 16) >> 1), b_k16 = (lane >> 3) & 1;

    auto issue = [&](int c, int st) {
        const int kb = c * 64;
        const uint32_t stb = sb + st * G2_ST;
#pragma unroll
        for (int it = 0; it < 4; it++) {
            const int r = lr + 32 * it;
            const uint32_t so = SWZ128((uint32_t)(r * 128 + lseg * 16));
            const size_t g = (size_t)(m0 + r) * GK + kb + lseg * 8;
            CP16(stb + so, Ah + g);
            CP16(stb + 16384 + so, Al + g);
            CP16(stb + 32768 + so, Bf + (size_t)(n0 + r) * GK + kb + lseg * 8);
        }
        CP_COMMIT();
    };

    issue(0, 0);
    issue(1, 1);
    for (int c = 0; c < 16; c++) {
        if (c + 1 < 16) CP_WAIT(1); else CP_WAIT(0);
        __syncthreads();
        if (c + 2 < 16) issue(c + 2, (c + 2) % 3);
        const uint32_t sAh = sb + (c % 3) * G2_ST;
        const uint32_t sAl = sAh + 16384;
        const uint32_t sB  = sAh + 32768;
#pragma unroll
        for (int kk = 0; kk < 4; kk++) {
            const uint32_t akoff = kk * 32 + a_k16 * 16;
            const uint32_t bkoff = kk * 32 + b_k16 * 16;
            uint32_t bf[2][4];
#pragma unroll
            for (int nj = 0; nj < 2; nj++) {
                const uint32_t off = SWZ128((uint32_t)((b_row + nj * 16) * 128) + bkoff);
                LDMX4(bf[nj][0], bf[nj][1], bf[nj][2], bf[nj][3], sB + off);
            }
#pragma unroll
            for (int mi = 0; mi < 4; mi++) {
                const uint32_t off = SWZ128((uint32_t)((a_row + mi * 16) * 128) + akoff);
                uint32_t ah[4], al[4];
                LDMX4(ah[0], ah[1], ah[2], ah[3], sAh + off);
                LDMX4(al[0], al[1], al[2], al[3], sAl + off);
#pragma unroll
                for (int nj = 0; nj < 2; nj++)
#pragma unroll
                    for (int q = 0; q < 2; q++)
                        MMA16816H(acc[mi][nj * 2 + q], ah, bf[nj][q * 2], bf[nj][q * 2 + 1]);
#pragma unroll
                for (int nj = 0; nj < 2; nj++)
#pragma unroll
                    for (int q = 0; q < 2; q++)
                        MMA16816H(acc[mi][nj * 2 + q], al, bf[nj][q * 2], bf[nj][q * 2 + 1]);
            }
        }
    }

    const int rl = lane >> 2, cl = (lane & 3) * 2;
#pragma unroll
    for (int mi = 0; mi < 4; mi++) {
        const int r_base = wm + mi * 16 + rl;
#pragma unroll
        for (int ni = 0; ni < 4; ni++) {
            const int cn = wn + ni * 8 + cl;
            const float2 b2 = *(const float2*)&bias[n0 + cn];
#pragma unroll
            for (int half = 0; half < 2; half++) {
                const int m = m0 + r_base + half * 8;
                float v0 = acc[mi][ni][half * 2 + 0] + b2.x;
                float v1 = acc[mi][ni][half * 2 + 1] + b2.y;
                if (mode == 0) {
                    float2 v; v.x = v0; v.y = v1;
                    *(float2*)&Cf[(size_t)m * N + n0 + cn] = v;
                } else {
                    const int b = m >> 11, t = m & 2047;
                    const int d = n0 + cn;
                    const int h = d >> 6, dk = d & 63;
                    const size_t off = (((size_t)(b * H_ + h)) * T_ + t) * DK_ + dk;
                    *(uint32_t*)(oVf + off) = pack_fp16(v0, v1);
                }
            }
        }
    }
}

// ---------------- attention (R16; A out fp16 hi/lo) ------------------------
#define ASM_QH 0
#define ASM_QL 16384
#define ASM_KV 32768
#define AKV_ST 49152
#define AKV_KH 0
#define AKV_KL 16384
#define AKV_VF 32768
#define ASM_TOT (32768 + 3 * AKV_ST)

__global__ __launch_bounds__(256, 1) void attn_mma(
    const __nv_bfloat16* __restrict__ Qh, const __nv_bfloat16* __restrict__ Ql,
    const __nv_bfloat16* __restrict__ Kh, const __nv_bfloat16* __restrict__ Kl,
    const __half* __restrict__ Vf,
    __half* __restrict__ Ah, __half* __restrict__ Al)
{
    extern __shared__ char smem[];
    const uint32_t sb = smem_u32(smem);
    const int tid = threadIdx.x, lane = tid & 31, wid = tid >> 5;
    const int qt = gridDim.x - 1 - blockIdx.x;
    const int q0 = qt * 128;
    const int h = blockIdx.y, b = blockIdx.z;
    const size_t hb = ((size_t)(b * H_ + h)) * T_ * DK_;

    {
#pragma unroll
        for (int it = 0; it < 4; it++) {
            const int u = tid + 256 * it;
            const int r = u >> 3, seg = u & 7;
            const uint32_t so = SWZ128((uint32_t)(r * 128 + seg * 16));
            const size_t g = hb + (size_t)(q0 + r) * DK_ + seg * 8;
            CP16(sb + ASM_QH + so, Qh + g);
            CP16(sb + ASM_QL + so, Ql + g);
        }
        CP_COMMIT();
    }

    auto issueKV = [&](int kt, int st) {
        const int k0 = kt * 128;
        const uint32_t stb = sb + ASM_KV + st * AKV_ST;
#pragma unroll
        for (int it = 0; it < 4; it++) {
            const int u = tid + 256 * it;
            const int r = u >> 3, seg = u & 7;
            const uint32_t so = SWZ128((uint32_t)(r * 128 + seg * 16));
            const size_t g = hb + (size_t)(k0 + r) * DK_ + seg * 8;
            CP16(stb + AKV_KH + so, Kh + g);
            CP16(stb + AKV_KL + so, Kl + g);
            CP16(stb + AKV_VF + so, Vf + g);
        }
        CP_COMMIT();
    };

    const int nkt = qt;
    issueKV(0, 0);
    if (nkt >= 1) { issueKV(1, 1); CP_WAIT(2); }
    else          { CP_WAIT(1); }
    __syncthreads();

    const int a_row = wid * 16 + (lane & 15), a_k16 = lane >> 4;
    uint32_t qfh[4][4], qfl[4][4];
#pragma unroll
    for (int kk = 0; kk < 4; kk++) {
        const uint32_t off = SWZ128((uint32_t)(a_row * 128 + kk * 32 + a_k16 * 16));
        LDMX4(qfh[kk][0], qfh[kk][1], qfh[kk][2], qfh[kk][3], sb + ASM_QH + off);
        LDMX4(qfl[kk][0], qfl[kk][1], qfl[kk][2], qfl[kk][3], sb + ASM_QL + off);
    }

    const int b_row = (lane & 7) + ((lane & 16) >> 1), b_k16 = (lane >> 3) & 1;
    const int vm = lane >> 3, vr = lane & 7;
    const int rr = lane >> 2, t2 = (lane & 3) * 2;

    float o[8][4];
#pragma unroll
    for (int i = 0; i < 8; i++)
#pragma unroll
        for (int j = 0; j < 4; j++) o[i][j] = 0.f;
    float m_r = -1e30f, m_r8 = -1e30f, l_r = 0.f, l_r8 = 0.f;

    for (int kt = 0; kt <= nkt; kt++) {
        if (kt + 1 <= nkt) CP_WAIT(1); else CP_WAIT(0);
        __syncthreads();
        if (kt + 2 <= nkt) issueKV(kt + 2, (kt + 2) % 3);
        const uint32_t stb = sb + ASM_KV + (kt % 3) * AKV_ST;
        const int k0 = kt * 128;

        float s[16][4];
#pragma unroll
        for (int i = 0; i < 16; i++)
#pragma unroll
            for (int j = 0; j < 4; j++) s[i][j] = 0.f;
#pragma unroll
        for (int kk = 0; kk < 4; kk++) {
#pragma unroll
            for (int nn = 0; nn < 8; nn++) {
                const uint32_t off = SWZ128((uint32_t)((nn * 16 + b_row) * 128 + kk * 32 + b_k16 * 16));
                uint32_t kh[4], kl[4];
                LDMX4(kh[0], kh[1], kh[2], kh[3], stb + AKV_KH + off);
                LDMX4(kl[0], kl[1], kl[2], kl[3], stb + AKV_KL + off);
                float* s0 = s[2 * nn];
                float* s1 = s[2 * nn + 1];
                MMA16816(s0, qfh[kk], kh[0], kh[1]);
                MMA16816(s0, qfl[kk], kh[0], kh[1]);
                MMA16816(s0, qfh[kk], kl[0], kl[1]);
                MMA16816(s1, qfh[kk], kh[2], kh[3]);
                MMA16816(s1, qfl[kk], kh[2], kh[3]);
                MMA16816(s1, qfh[kk], kl[2], kl[3]);
            }
        }

        const bool diag = (k0 == q0);
        const int qi_r = q0 + wid * 16 + rr;
#pragma unroll
        for (int ni = 0; ni < 16; ni++) {
            const int kc = k0 + ni * 8 + t2;
#pragma unroll
            for (int e = 0; e < 4; e++) {
                float v = s[ni][e] * 0.125f;
                if (diag) {
                    const int kj = kc + (e & 1);
                    const int qi = qi_r + ((e >> 1) << 3);
                    if (kj > qi) v = -1e30f;
                }
                s[ni][e] = v;
            }
        }

        float rmr = -1e30f, rm8 = -1e30f;
#pragma unroll
        for (int ni = 0; ni < 16; ni++) {
            rmr = fmaxf(rmr, fmaxf(s[ni][0], s[ni][1]));
            rm8 = fmaxf(rm8, fmaxf(s[ni][2], s[ni][3]));
        }
        rmr = fmaxf(rmr, __shfl_xor_sync(0xffffffffu, rmr, 1));
        rmr = fmaxf(rmr, __shfl_xor_sync(0xffffffffu, rmr, 2));
        rm8 = fmaxf(rm8, __shfl_xor_sync(0xffffffffu, rm8, 1));
        rm8 = fmaxf(rm8, __shfl_xor_sync(0xffffffffu, rm8, 2));

        const float mnr = fmaxf(m_r, rmr), mn8 = fmaxf(m_r8, rm8);
        const float ar = __expf(m_r - mnr), a8 = __expf(m_r8 - mn8);
        m_r = mnr; m_r8 = mn8;
        l_r *= ar; l_r8 *= a8;
#pragma unroll
        for (int dn = 0; dn < 8; dn++) {
            o[dn][0] *= ar; o[dn][1] *= ar; o[dn][2] *= a8; o[dn][3] *= a8;
        }

#pragma unroll
        for (int kk = 0; kk < 8; kk++) {
            float p0 = __expf(s[2 * kk][0] - m_r);
            float p1 = __expf(s[2 * kk][1] - m_r);
            float p2 = __expf(s[2 * kk][2] - m_r8);
            float p3 = __expf(s[2 * kk][3] - m_r8);
            float p4 = __expf(s[2 * kk + 1][0] - m_r);
            float p5 = __expf(s[2 * kk + 1][1] - m_r);
            float p6 = __expf(s[2 * kk + 1][2] - m_r8);
            float p7 = __expf(s[2 * kk + 1][3] - m_r8);
            l_r  += p0 + p1 + p4 + p5;
            l_r8 += p2 + p3 + p6 + p7;

            uint32_t pH[4];
            pH[0] = pack_fp16(p0, p1);
            pH[1] = pack_fp16(p2, p3);
            pH[2] = pack_fp16(p4, p5);
            pH[3] = pack_fp16(p6, p7);
#pragma unroll
            for (int dp = 0; dp < 4; dp++) {
                const uint32_t off = SWZ128((uint32_t)(
                    (kk * 16 + (vm & 1) * 8 + vr) * 128 + (vm >> 1) * 16 + dp * 32));
                uint32_t vh[4];
                LDMX4T(vh[0], vh[1], vh[2], vh[3], stb + AKV_VF + off);
                MMA16816H(o[2 * dp], pH, vh[0], vh[1]);
                MMA16816H(o[2 * dp + 1], pH, vh[2], vh[3]);
            }
        }
    }

    l_r  += __shfl_xor_sync(0xffffffffu, l_r, 1);
    l_r  += __shfl_xor_sync(0xffffffffu, l_r, 2);
    l_r8 += __shfl_xor_sync(0xffffffffu, l_r8, 1);
    l_r8 += __shfl_xor_sync(0xffffffffu, l_r8, 2);
    const float ir = 1.f / l_r, i8 = 1.f / l_r8;
    const int trow = q0 + wid * 16 + rr;
#pragma unroll
    for (int dn = 0; dn < 8; dn++) {
        float v0 = o[dn][0] * ir, v1 = o[dn][1] * ir;
        float v2 = o[dn][2] * i8, v3 = o[dn][3] * i8;
        const int col = h * DK_ + dn * 8 + t2;
        size_t o1 = ((size_t)(b * T_ + trow)) * D_ + col;
        size_t o2 = ((size_t)(b * T_ + trow + 8)) * D_ + col;
        uint32_t hp, lw;
        split2h(v0, v1, hp, lw);
        *(uint32_t*)(Ah + o1) = hp; *(uint32_t*)(Al + o1) = lw;
        split2h(v2, v3, hp, lw);
        *(uint32_t*)(Ah + o2) = hp; *(uint32_t*)(Al + o2) = lw;
    }
}

// ---------------------------------------------------------------------------
extern "C" void kernel_launch(void* const* d_in, const int* in_sizes, int n_in,
                              void* d_out, int out_size)
{
    const float* x     = (const float*)d_in[0];
    const float* W_qkv = (const float*)d_in[1];
    const float* b_qkv = (const float*)d_in[2];
    const float* W_o   = (const float*)d_in[3];
    const float* b_o   = (const float*)d_in[4];

    __nv_bfloat16 *Qh, *Ql, *Kh, *Kl, *Xh, *Xl, *Wqh, *Wql;
    __half *Vf, *Xfh, *Xfl, *Afh, *Afl, *Wvf, *Wof;
    cudaGetSymbolAddress((void**)&Qh, g_Qh); cudaGetSymbolAddress((void**)&Ql, g_Ql);
    cudaGetSymbolAddress((void**)&Kh, g_Kh); cudaGetSymbolAddress((void**)&Kl, g_Kl);
    cudaGetSymbolAddress((void**)&Vf, g_Vf);
    cudaGetSymbolAddress((void**)&Xh, g_Xh); cudaGetSymbolAddress((void**)&Xl, g_Xl);
    cudaGetSymbolAddress((void**)&Xfh, g_Xfh); cudaGetSymbolAddress((void**)&Xfl, g_Xfl);
    cudaGetSymbolAddress((void**)&Afh, g_Afh); cudaGetSymbolAddress((void**)&Afl, g_Afl);
    cudaGetSymbolAddress((void**)&Wqh, g_Wqh); cudaGetSymbolAddress((void**)&Wql, g_Wql);
    cudaGetSymbolAddress((void**)&Wvf, g_Wvf); cudaGetSymbolAddress((void**)&Wof, g_Wof);

    const int M = B_ * T_;

    prep_all<<<PREP_SPLIT_BLKS + PREP_WQK_BLKS + PREP_WV_BLKS + PREP_WO_BLKS, 256>>>(
        x, Xh, Xl, Xfh, Xfl, W_qkv, Wqh, Wql, Wvf, W_o, Wof);

    cudaFuncSetAttribute(gemm_mma, cudaFuncAttributeMaxDynamicSharedMemorySize, GSM_TOT);
    cudaFuncSetAttribute(gemm_2t, cudaFuncAttributeMaxDynamicSharedMemorySize, G2_TOT);
    cudaFuncSetAttribute(attn_mma, cudaFuncAttributeMaxDynamicSharedMemorySize, ASM_TOT);

    // 1a) Q,K projection (3-term bf16) -> bf16 hi/lo head-major
    {
        dim3 grid(2 * D_ / 128, M / 128);
        gemm_mma<<<grid, 256, GSM_TOT>>>(Xh, Xl, Wqh, Wql, b_qkv, Qh, Ql, Kh, Kl);
    }
    // 1b) V projection (2-term fp16) -> fp16 head-major
    {
        dim3 grid(D_ / 128, M / 128);
        gemm_2t<<<grid, 256, G2_TOT>>>(Xfh, Xfl, Wvf, b_qkv + 2 * D_, nullptr, Vf, D_, 1);
    }
    // 2) causal flash attention -> A fp16 hi/lo
    {
        dim3 grid(T_ / 128, H_, B_);
        attn_mma<<<grid, 256, ASM_TOT>>>(Qh, Ql, Kh, Kl, Vf, Afh, Afl);
    }
    // 3) output projection (2-term fp16) -> fp32 d_out
    {
        dim3 grid(D_ / 128, M / 128);
        gemm_2t<<<grid, 256, G2_TOT>>>(Afh, Afl, Wof, b_o, (float*)d_out, nullptr, D_, 0);
    }
}